// round 15
// baseline (speedup 1.0000x reference)
#include <cuda_runtime.h>
#include <cuda_bf16.h>
#include <cstdint>
#include <math.h>

// ---------------- problem constants ----------------
#define BATCHN 8
#define TLEN   1024
#define DM     512
#define HH     1024
#define K3H    3072
#define NWALL  6144
#define NTOK   8192
#define GOUT   2048
#define FFND   2048
#define NE     8
#define GRU_CTAS 128
#define DIR_CTAS 64
// weights 192KB + hs 32KB (sred aliased into hs)
#define GRU_SMEM ((16 * 3 * HH + BATCHN * HH) * 4)
#define HMMA_SMEM 65536

typedef unsigned long long u64;
typedef __nv_bfloat16 bf16;

// ---------------- packed fp32x2 helpers (GRU) ----------------
__device__ __forceinline__ u64 pk2(float x) {
    u64 r; asm("mov.b64 %0, {%1, %1};" : "=l"(r) : "f"(x)); return r;
}
__device__ __forceinline__ void fma2(u64& d, u64 a, u64 b) {
    asm("fma.rn.f32x2 %0, %1, %2, %0;" : "+l"(d) : "l"(a), "l"(b));
}
__device__ __forceinline__ float2 upk(u64 v) {
    float2 f; asm("mov.b64 {%0, %1}, %2;" : "=f"(f.x), "=f"(f.y) : "l"(v)); return f;
}
union F4U { float4 f; u64 u[2]; };

// ---------------- HMMA helpers ----------------
__device__ __forceinline__ uint32_t smem_u32(const void* p) {
    uint32_t a;
    asm("{ .reg .u64 t; cvta.to.shared.u64 t, %1; cvt.u32.u64 %0, t; }" : "=r"(a) : "l"(p));
    return a;
}
__device__ __forceinline__ void ldsm4(uint32_t& r0, uint32_t& r1, uint32_t& r2,
                                      uint32_t& r3, uint32_t addr) {
    asm volatile("ldmatrix.sync.aligned.m8n8.x4.shared.b16 {%0,%1,%2,%3}, [%4];"
                 : "=r"(r0), "=r"(r1), "=r"(r2), "=r"(r3) : "r"(addr));
}
__device__ __forceinline__ void mma_bf16(float* d, const uint32_t* a,
                                         uint32_t b0, uint32_t b1) {
    asm volatile("mma.sync.aligned.m16n8k16.row.col.f32.bf16.bf16.f32 "
        "{%0,%1,%2,%3}, {%4,%5,%6,%7}, {%8,%9}, {%0,%1,%2,%3};"
        : "+f"(d[0]), "+f"(d[1]), "+f"(d[2]), "+f"(d[3])
        : "r"(a[0]), "r"(a[1]), "r"(a[2]), "r"(a[3]), "r"(b0), "r"(b1));
}
__device__ __forceinline__ uint32_t toff(int r, int s) {
    return (uint32_t)(r * 64 + ((s ^ ((r >> 1) & 3)) << 4));
}

// ---------------- static device scratch ----------------
__device__ float g_xg[(size_t)NTOK * NWALL];
__device__ float g_flat[(size_t)NTOK * GOUT];
__device__ float g_obuf[(size_t)NTOK * 2 * DM];
__device__ float g_hbuf[2][2][BATCHN * HH];
__device__ int   g_list[NE][NTOK];
__device__ int   g_cnt[NE];
__device__ float g_wt[NTOK * 2];
__device__ float g_Psum[NE];
__device__ float g_zsum;
__device__ volatile int g_flag[2][DIR_CTAS][32];   // padded: 1 flag / 128B line
// bf16 split operands
__device__ bf16 g_xhi[(size_t)NTOK * DM],    g_xlo[(size_t)NTOK * DM];
__device__ bf16 g_whi[(size_t)NWALL * DM],   g_wlo[(size_t)NWALL * DM];
__device__ bf16 g_fhi[(size_t)NTOK * GOUT],  g_flo[(size_t)NTOK * GOUT];
__device__ bf16 g_w1hi[(size_t)NE * GOUT * FFND], g_w1lo[(size_t)NE * GOUT * FFND];
__device__ bf16 g_h1hi[(size_t)NTOK * 2 * FFND],  g_h1lo[(size_t)NTOK * 2 * FFND];
__device__ bf16 g_w2hi[(size_t)NE * FFND * DM],   g_w2lo[(size_t)NE * FFND * DM];

extern __shared__ char smem_raw[];

// ---------------- init ----------------
__global__ void init_kernel() {
    int i = blockIdx.x * blockDim.x + threadIdx.x;
    float* h0 = &g_hbuf[0][0][0];
    if (i < 2 * 2 * BATCHN * HH) h0[i] = 0.f;
    if (i < NE) { g_cnt[i] = 0; g_Psum[i] = 0.f; }
    if (i < 2 * DIR_CTAS) g_flag[i >> 6][i & 63][0] = 0;
    if (i == 0) g_zsum = 0.f;
}

// ---------------- bf16 split conversions ----------------
__global__ void split_kernel(const float* __restrict__ src,
                             bf16* __restrict__ hi, bf16* __restrict__ lo, size_t n) {
    size_t i = (size_t)blockIdx.x * blockDim.x + threadIdx.x;
    if (i >= n) return;
    float x = src[i];
    bf16 h = __float2bfloat16(x);
    hi[i] = h;
    lo[i] = __float2bfloat16(x - __bfloat162float(h));
}

// W [e][K][N] -> hi/lo [e][N][K]
__global__ void tsplit_kernel(const float* __restrict__ W,
                              bf16* __restrict__ hi, bf16* __restrict__ lo, int K, int N) {
    __shared__ float tile[32][33];
    int e = blockIdx.z;
    const float* We = W + (size_t)e * K * N;
    bf16* hie = hi + (size_t)e * K * N;
    bf16* loe = lo + (size_t)e * K * N;
    int k0 = blockIdx.x * 32, n0 = blockIdx.y * 32;
    int tx = threadIdx.x, ty = threadIdx.y;
    #pragma unroll
    for (int r = 0; r < 32; r += 8)
        tile[ty + r][tx] = We[(size_t)(k0 + ty + r) * N + n0 + tx];
    __syncthreads();
    #pragma unroll
    for (int r = 0; r < 32; r += 8) {
        float x = tile[tx][ty + r];
        bf16 h = __float2bfloat16(x);
        size_t o = (size_t)(n0 + ty + r) * K + k0 + tx;
        hie[o] = h;
        loe[o] = __float2bfloat16(x - __bfloat162float(h));
    }
}

// ---------------- HMMA bf16x3 GEMM (R13 winner, unchanged) ----------------------
__global__ void __launch_bounds__(256) hmma_gemm(
    const bf16* __restrict__ Ahi, const bf16* __restrict__ Alo, int lda,
    const bf16* __restrict__ Bhi, const bf16* __restrict__ Blo, int ldb,
    const float* __restrict__ bias, int biasPerExp,
    float* Cf, bf16* Chi, bf16* Clo, int ldc,
    int M, int N, int K,
    int useList, int aDiv, int act, long bStrideB)
{
    char* smem = smem_raw;
    const int tid = threadIdx.x;
    const int* glist = nullptr;
    if (useList) {
        int e = blockIdx.z;
        M = g_cnt[e];
        glist = g_list[e];
        Bhi += (size_t)bStrideB * e;
        Blo += (size_t)bStrideB * e;
        bias += (size_t)biasPerExp * e;
    }
    int m0 = blockIdx.y * 128;
    if (m0 >= M) return;
    int n0 = blockIdx.x * 128;

    uint32_t sb = smem_u32(smem);
    int warp = tid >> 5, lane = tid & 31;
    int wm = warp & 3, wn = warp >> 2;

    int srow = tid >> 1;
    int ss0 = (tid & 1) * 2;
    int mA = m0 + srow;
    bool aValid = (mA < M);
    size_t arow = 0;
    if (aValid) { if (glist) { int gv = glist[mA]; arow = (size_t)(aDiv ? (gv >> 1) : gv); }
                  else arow = (size_t)mA; }
    const uint4* Aph = (const uint4*)(Ahi + arow * (size_t)lda);
    const uint4* Apl = (const uint4*)(Alo + arow * (size_t)lda);
    const uint4* Bph = (const uint4*)(Bhi + (size_t)(n0 + srow) * ldb);
    const uint4* Bpl = (const uint4*)(Blo + (size_t)(n0 + srow) * ldb);
    uint32_t wo0 = toff(srow, ss0);
    uint32_t wo1 = toff(srow, ss0 + 1);

    int laneRowA = (((lane >> 3) & 1) << 3) + (lane & 7);
    int laneSegA = lane >> 4;
    int laneRowB = ((lane >> 4) << 3) + (lane & 7);
    int laneSegB = (lane >> 3) & 1;

    float acc[2][8][4];
    #pragma unroll
    for (int a = 0; a < 2; a++)
        #pragma unroll
        for (int b = 0; b < 8; b++)
            #pragma unroll
            for (int c = 0; c < 4; c++) acc[a][b][c] = 0.f;

    const uint4 z4 = make_uint4(0u, 0u, 0u, 0u);
    int nchunks = K >> 5;

    uint4 va0 = aValid ? __ldg(&Aph[ss0]) : z4;
    uint4 va1 = aValid ? __ldg(&Aph[ss0 + 1]) : z4;
    uint4 vb0 = aValid ? __ldg(&Apl[ss0]) : z4;
    uint4 vb1 = aValid ? __ldg(&Apl[ss0 + 1]) : z4;
    uint4 vc0 = __ldg(&Bph[ss0]);
    uint4 vc1 = __ldg(&Bph[ss0 + 1]);
    uint4 vd0 = __ldg(&Bpl[ss0]);
    uint4 vd1 = __ldg(&Bpl[ss0 + 1]);

    int buf = 0;
    for (int c = 0; c < nchunks; c++) {
        char* bp = smem + buf * 32768;
        *(uint4*)(bp + wo0)          = va0;
        *(uint4*)(bp + wo1)          = va1;
        *(uint4*)(bp + 8192  + wo0)  = vb0;
        *(uint4*)(bp + 8192  + wo1)  = vb1;
        *(uint4*)(bp + 16384 + wo0)  = vc0;
        *(uint4*)(bp + 16384 + wo1)  = vc1;
        *(uint4*)(bp + 24576 + wo0)  = vd0;
        *(uint4*)(bp + 24576 + wo1)  = vd1;
        __syncthreads();

        if (c + 1 < nchunks) {
            int gs = (c + 1) * 4 + ss0;
            va0 = aValid ? __ldg(&Aph[gs]) : z4;
            va1 = aValid ? __ldg(&Aph[gs + 1]) : z4;
            vb0 = aValid ? __ldg(&Apl[gs]) : z4;
            vb1 = aValid ? __ldg(&Apl[gs + 1]) : z4;
            vc0 = __ldg(&Bph[gs]);
            vc1 = __ldg(&Bph[gs + 1]);
            vd0 = __ldg(&Bpl[gs]);
            vd1 = __ldg(&Bpl[gs + 1]);
        }

        uint32_t base = sb + buf * 32768;
        #pragma unroll
        for (int kstep = 0; kstep < 2; kstep++) {
            uint32_t ah[2][4], al[2][4];
            #pragma unroll
            for (int mt = 0; mt < 2; mt++) {
                int r = wm * 32 + mt * 16 + laneRowA;
                int s = kstep * 2 + laneSegA;
                uint32_t ad = base + toff(r, s);
                ldsm4(ah[mt][0], ah[mt][1], ah[mt][2], ah[mt][3], ad);
                ldsm4(al[mt][0], al[mt][1], al[mt][2], al[mt][3], ad + 8192);
            }
            #pragma unroll
            for (int np = 0; np < 4; np++) {
                int r = wn * 64 + np * 16 + laneRowB;
                int s = kstep * 2 + laneSegB;
                uint32_t bd = base + 16384 + toff(r, s);
                uint32_t bh[4], bl[4];
                ldsm4(bh[0], bh[1], bh[2], bh[3], bd);
                ldsm4(bl[0], bl[1], bl[2], bl[3], bd + 8192);
                #pragma unroll
                for (int mt = 0; mt < 2; mt++) {
                    mma_bf16(acc[mt][np * 2],     ah[mt], bh[0], bh[1]);
                    mma_bf16(acc[mt][np * 2 + 1], ah[mt], bh[2], bh[3]);
                    mma_bf16(acc[mt][np * 2],     ah[mt], bl[0], bl[1]);
                    mma_bf16(acc[mt][np * 2 + 1], ah[mt], bl[2], bl[3]);
                    mma_bf16(acc[mt][np * 2],     al[mt], bh[0], bh[1]);
                    mma_bf16(acc[mt][np * 2 + 1], al[mt], bh[2], bh[3]);
                }
            }
        }
        __syncthreads();
        buf ^= 1;
    }

    #pragma unroll
    for (int mt = 0; mt < 2; mt++) {
        #pragma unroll
        for (int rr = 0; rr < 2; rr++) {
            int m_loc = wm * 32 + mt * 16 + rr * 8 + (lane >> 2);
            int m = m0 + m_loc;
            if (m >= M) continue;
            size_t crow = glist ? (size_t)glist[m] : (size_t)m;
            #pragma unroll
            for (int nt = 0; nt < 8; nt++) {
                int n = n0 + wn * 64 + nt * 8 + (lane & 3) * 2;
                float v0 = acc[mt][nt][rr * 2]     + __ldg(&bias[n]);
                float v1 = acc[mt][nt][rr * 2 + 1] + __ldg(&bias[n + 1]);
                if (act) {
                    v0 = 0.5f * v0 * (1.0f + erff(v0 * 0.70710678118654752f));
                    v1 = 0.5f * v1 * (1.0f + erff(v1 * 0.70710678118654752f));
                }
                size_t o = crow * (size_t)ldc + n;
                if (Cf) {
                    *(float2*)(Cf + o) = make_float2(v0, v1);
                } else {
                    bf16 h0 = __float2bfloat16(v0);
                    bf16 h1 = __float2bfloat16(v1);
                    Chi[o]     = h0;
                    Chi[o + 1] = h1;
                    Clo[o]     = __float2bfloat16(v0 - __bfloat162float(h0));
                    Clo[o + 1] = __float2bfloat16(v1 - __bfloat162float(h1));
                }
            }
        }
    }
}

// ---------------- padded flag-array grid barrier (per direction) ---------------
__device__ __forceinline__ void grid_sync_dir(int dir, int cta, int step) {
    __syncthreads();
    if (threadIdx.x == 0) {
        __threadfence();
        g_flag[dir][cta][0] = step;
    }
    if (threadIdx.x < DIR_CTAS) {
        while (g_flag[dir][threadIdx.x][0] < step) __nanosleep(32);
    }
    __syncthreads();
}

// ---------------- persistent bidirectional GRU: quarter-k x quad-j remap -------
// 128 CTAs x 512 threads. warp = (kq in 4, jq in 4): 4 hidden units over a
// quarter of k -> h crossbar traffic halved vs R7 (each h read feeds 4 j).
// lane = (bq in 4, kg in 8): 2 batches per lane. sred aliased onto hs (hp is
// prefetched from global, so hs is dead after the compute phase).
__global__ void __launch_bounds__(512) gru_persist(
    const float* __restrict__ Whh, const float* __restrict__ bhh)
{
    float* smem = (float*)smem_raw;
    float* sw   = smem;                        // [16 jj][3 g][1024]
    float* hs   = smem + 16 * 3 * HH;          // [8][1024]
    float* sred = hs;                          // alias (16 warps x 96 floats)
    int bx = blockIdx.x;
    int dir = bx >> 6;
    int cta = bx & 63;
    int warp = threadIdx.x >> 5;
    int lane = threadIdx.x & 31;

    int kq = warp >> 2;             // k quarter 0..3
    int jq = warp & 3;              // j quad 0..3
    int bq = lane >> 3;             // batch pair 0..3 (b = 2bq, 2bq+1)
    int kg = lane & 7;              // k group 0..7

    // stage weights (once): warp w loads jj=w's 3 gate rows
    {
        int jglob = cta * 16 + warp;
        const float* Wb = Whh + (size_t)dir * K3H * HH;
        #pragma unroll
        for (int g = 0; g < 3; g++) {
            const float4* src = (const float4*)(Wb + (size_t)(g * HH + jglob) * HH);
            float4* dst = (float4*)(sw + (warp * 3 + g) * HH);
            for (int kk = lane; kk < HH / 4; kk += 32)
                dst[kk] = src[kk];
        }
    }

    // tail role: warps 0-7, lanes 0-15: tjj = warp*2 + (lane>>3), tb = lane&7
    bool tail = (warp < 8) && (lane < 16);
    int tjj = warp * 2 + (lane >> 3);
    int tb  = lane & 7;
    int tj  = cta * 16 + tjj;
    int jq_t = tjj >> 2, jl_t = tjj & 3;
    float bh_r = 0.f, bh_z = 0.f, bh_n = 0.f;
    if (tail) {
        const float* bhp = bhh + dir * K3H;
        bh_r = bhp[tj]; bh_z = bhp[HH + tj]; bh_n = bhp[2 * HH + tj];
    }

    const F4U* wp_[4][3];
    #pragma unroll
    for (int jl = 0; jl < 4; jl++)
        #pragma unroll
        for (int g = 0; g < 3; g++)
            wp_[jl][g] = (const F4U*)(sw + ((jq * 4 + jl) * 3 + g) * HH);
    const F4U* h4 = (const F4U*)hs;
    const int kbase4 = kq * 64;     // float4 units

    for (int s = 0; s < TLEN; s++) {
        int t = dir ? (TLEN - 1 - s) : s;

        // tail prefetch: gate inputs + previous h (hs is aliased by sred, so hp
        // must come from global)
        float xr = 0.f, xz = 0.f, xn = 0.f, hp = 0.f;
        if (tail) {
            const float* xgr = g_xg + (size_t)(tb * TLEN + t) * NWALL + (size_t)dir * K3H;
            xr = __ldg(&xgr[tj]);
            xz = __ldg(&xgr[HH + tj]);
            xn = __ldg(&xgr[2 * HH + tj]);
            hp = __ldcg(&g_hbuf[s & 1][dir][tb * HH + tj]);
        }

        // refresh hidden state (L1-bypassed: lines written by other SMs)
        const float4* hprev = (const float4*)&g_hbuf[s & 1][dir][0];
        float4* hs4 = (float4*)hs;
        #pragma unroll
        for (int idx = threadIdx.x; idx < BATCHN * HH / 4; idx += 512)
            hs4[idx] = __ldcg(&hprev[idx]);
        __syncthreads();

        u64 acc[4][3][2];
        #pragma unroll
        for (int jl = 0; jl < 4; jl++)
            #pragma unroll
            for (int g = 0; g < 3; g++)
                #pragma unroll
                for (int b = 0; b < 2; b++) acc[jl][g][b] = 0ull;

        #pragma unroll
        for (int i = 0; i < 8; i++) {
            int kx = kbase4 + i * 8 + kg;
            F4U hv0 = h4[(bq * 2 + 0) * 256 + kx];
            F4U hv1 = h4[(bq * 2 + 1) * 256 + kx];
            #pragma unroll
            for (int g = 0; g < 3; g++) {
                F4U w0 = wp_[0][g][kx], w1 = wp_[1][g][kx];
                F4U w2 = wp_[2][g][kx], w3 = wp_[3][g][kx];
                fma2(acc[0][g][0], w0.u[0], hv0.u[0]);
                fma2(acc[0][g][0], w0.u[1], hv0.u[1]);
                fma2(acc[0][g][1], w0.u[0], hv1.u[0]);
                fma2(acc[0][g][1], w0.u[1], hv1.u[1]);
                fma2(acc[1][g][0], w1.u[0], hv0.u[0]);
                fma2(acc[1][g][0], w1.u[1], hv0.u[1]);
                fma2(acc[1][g][1], w1.u[0], hv1.u[0]);
                fma2(acc[1][g][1], w1.u[1], hv1.u[1]);
                fma2(acc[2][g][0], w2.u[0], hv0.u[0]);
                fma2(acc[2][g][0], w2.u[1], hv0.u[1]);
                fma2(acc[2][g][1], w2.u[0], hv1.u[0]);
                fma2(acc[2][g][1], w2.u[1], hv1.u[1]);
                fma2(acc[3][g][0], w3.u[0], hv0.u[0]);
                fma2(acc[3][g][0], w3.u[1], hv0.u[1]);
                fma2(acc[3][g][1], w3.u[0], hv1.u[0]);
                fma2(acc[3][g][1], w3.u[1], hv1.u[1]);
            }
        }

        // collapse pairs + reduce over the 8 kg lanes (xor < 8 keeps bq)
        float red[4][3][2];
        #pragma unroll
        for (int jl = 0; jl < 4; jl++)
            #pragma unroll
            for (int g = 0; g < 3; g++)
                #pragma unroll
                for (int b = 0; b < 2; b++) {
                    float2 p = upk(acc[jl][g][b]);
                    red[jl][g][b] = p.x + p.y;
                }
        #pragma unroll
        for (int off = 4; off > 0; off >>= 1)
            #pragma unroll
            for (int jl = 0; jl < 4; jl++)
                #pragma unroll
                for (int g = 0; g < 3; g++)
                    #pragma unroll
                    for (int b = 0; b < 2; b++)
                        red[jl][g][b] += __shfl_xor_sync(0xffffffffu, red[jl][g][b], off);

        __syncthreads();   // all h reads complete before aliasing hs with sred

        if (kg == 0) {
            float* dst = sred + warp * 96;
            #pragma unroll
            for (int jl = 0; jl < 4; jl++)
                #pragma unroll
                for (int g = 0; g < 3; g++)
                    #pragma unroll
                    for (int b = 0; b < 2; b++)
                        dst[(jl * 3 + g) * 8 + bq * 2 + b] = red[jl][g][b];
        }
        __syncthreads();

        if (tail) {
            int base = (jl_t * 3) * 8 + tb;
            float hr = bh_r, hz = bh_z, hn = bh_n;
            #pragma unroll
            for (int kk = 0; kk < 4; kk++) {
                const float* rp = sred + (kk * 4 + jq_t) * 96 + base;
                hr += rp[0];
                hz += rp[8];
                hn += rp[16];
            }
            float r  = 1.f / (1.f + expf(-(xr + hr)));
            float z  = 1.f / (1.f + expf(-(xz + hz)));
            float nn = tanhf(xn + r * hn);
            float hnew = (1.f - z) * nn + z * hp;
            g_hbuf[(s + 1) & 1][dir][tb * HH + tj] = hnew;
            float lrel = hnew > 0.f ? hnew : 0.01f * hnew;
            size_t o = (size_t)(tb * TLEN + t) * GOUT + dir * HH + tj;
            g_flat[o] = lrel;
            bf16 fh = __float2bfloat16(lrel);
            g_fhi[o] = fh;
            g_flo[o] = __float2bfloat16(lrel - __bfloat162float(fh));
        }
        grid_sync_dir(dir, cta, s + 1);
    }
}

// ---------------- gating: warp per token ----------------
__global__ void gate_kernel(const float* __restrict__ gW, const float* __restrict__ gb) {
    int gwid = (blockIdx.x * blockDim.x + threadIdx.x) >> 5;
    int lane = threadIdx.x & 31;
    if (gwid >= NTOK) return;
    const float* f = g_flat + (size_t)gwid * GOUT;
    float acc[NE];
    #pragma unroll
    for (int e = 0; e < NE; e++) acc[e] = 0.f;
    for (int k = lane; k < GOUT; k += 32) {
        float fv = f[k];
        #pragma unroll
        for (int e = 0; e < NE; e++) acc[e] = fmaf(fv, gW[e * GOUT + k], acc[e]);
    }
    #pragma unroll
    for (int e = 0; e < NE; e++)
        #pragma unroll
        for (int off = 16; off > 0; off >>= 1)
            acc[e] += __shfl_xor_sync(0xffffffffu, acc[e], off);

    if (lane == 0) {
        float l[NE], mx = -1e30f;
        #pragma unroll
        for (int e = 0; e < NE; e++) { l[e] = acc[e] + gb[e]; mx = fmaxf(mx, l[e]); }
        float se = 0.f;
        #pragma unroll
        for (int e = 0; e < NE; e++) se += expf(l[e] - mx);
        float lse = mx + logf(se);
        float sc[NE];
        #pragma unroll
        for (int e = 0; e < NE; e++) sc[e] = expf(l[e] - lse);
        int e0 = 0; float s0 = sc[0];
        #pragma unroll
        for (int e = 1; e < NE; e++) if (sc[e] > s0) { s0 = sc[e]; e0 = e; }
        int e1 = -1; float s1 = -1e30f;
        #pragma unroll
        for (int e = 0; e < NE; e++) if (e != e0 && sc[e] > s1) { s1 = sc[e]; e1 = e; }
        float inv = 1.f / (s0 + s1);
        int p0 = atomicAdd(&g_cnt[e0], 1);
        g_list[e0][p0] = gwid * 2;
        int p1 = atomicAdd(&g_cnt[e1], 1);
        g_list[e1][p1] = gwid * 2 + 1;
        g_wt[gwid * 2]     = s0 * inv;
        g_wt[gwid * 2 + 1] = s1 * inv;
        atomicAdd(&g_zsum, lse * lse);
        #pragma unroll
        for (int e = 0; e < NE; e++) atomicAdd(&g_Psum[e], sc[e]);
    }
}

// ---------------- deterministic combine ----------------
__global__ void combine_kernel(float* __restrict__ out) {
    int idx = blockIdx.x * blockDim.x + threadIdx.x;
    if (idx >= NTOK * DM) return;
    int t = idx >> 9;
    int d = idx & (DM - 1);
    out[idx] = g_wt[2 * t]     * g_obuf[(size_t)(2 * t) * DM + d]
             + g_wt[2 * t + 1] * g_obuf[(size_t)(2 * t + 1) * DM + d];
}

// ---------------- aux loss scalar ----------------
__global__ void aux_kernel(float* out, int out_size) {
    if (out_size <= NTOK * DM) return;
    float s = 0.f;
    #pragma unroll
    for (int e = 0; e < NE; e++)
        s += ((float)g_cnt[e] / (float)NTOK) * (g_Psum[e] / (float)NTOK);
    out[NTOK * DM] = 0.01f * (float)NE * s + 0.001f * (g_zsum / (float)NTOK);
}

// ---------------- launch ----------------
extern "C" void kernel_launch(void* const* d_in, const int* in_sizes, int n_in,
                              void* d_out, int out_size) {
    const float* x   = (const float*)d_in[0];
    const float* Wih = (const float*)d_in[1];
    const float* Whh = (const float*)d_in[2];
    const float* bih = (const float*)d_in[3];
    const float* bhh = (const float*)d_in[4];
    const float* gW  = (const float*)d_in[5];
    const float* gb  = (const float*)d_in[6];
    const float* W1  = (const float*)d_in[7];
    const float* b1  = (const float*)d_in[8];
    const float* W2  = (const float*)d_in[9];
    const float* b2  = (const float*)d_in[10];
    float* out = (float*)d_out;

    float *p_xg, *p_flat, *p_obuf;
    cudaGetSymbolAddress((void**)&p_xg,   g_xg);
    cudaGetSymbolAddress((void**)&p_flat, g_flat);
    cudaGetSymbolAddress((void**)&p_obuf, g_obuf);
    bf16 *p_xhi, *p_xlo, *p_whi, *p_wlo, *p_fhi, *p_flo;
    bf16 *p_w1hi, *p_w1lo, *p_h1hi, *p_h1lo, *p_w2hi, *p_w2lo;
    cudaGetSymbolAddress((void**)&p_xhi,  g_xhi);
    cudaGetSymbolAddress((void**)&p_xlo,  g_xlo);
    cudaGetSymbolAddress((void**)&p_whi,  g_whi);
    cudaGetSymbolAddress((void**)&p_wlo,  g_wlo);
    cudaGetSymbolAddress((void**)&p_fhi,  g_fhi);
    cudaGetSymbolAddress((void**)&p_flo,  g_flo);
    cudaGetSymbolAddress((void**)&p_w1hi, g_w1hi);
    cudaGetSymbolAddress((void**)&p_w1lo, g_w1lo);
    cudaGetSymbolAddress((void**)&p_h1hi, g_h1hi);
    cudaGetSymbolAddress((void**)&p_h1lo, g_h1lo);
    cudaGetSymbolAddress((void**)&p_w2hi, g_w2hi);
    cudaGetSymbolAddress((void**)&p_w2lo, g_w2lo);

    cudaFuncSetAttribute(gru_persist,
                         cudaFuncAttributeMaxDynamicSharedMemorySize, GRU_SMEM);
    cudaFuncSetAttribute(hmma_gemm,
                         cudaFuncAttributeMaxDynamicSharedMemorySize, HMMA_SMEM);

    init_kernel<<<256, 256>>>();

    // bf16 splits (flat split fused into GRU tail)
    split_kernel<<<(NTOK * DM + 255) / 256, 256>>>(x, p_xhi, p_xlo, (size_t)NTOK * DM);
    split_kernel<<<(NWALL * DM + 255) / 256, 256>>>(Wih, p_whi, p_wlo, (size_t)NWALL * DM);
    tsplit_kernel<<<dim3(GOUT / 32, FFND / 32, NE), dim3(32, 8)>>>(W1, p_w1hi, p_w1lo, GOUT, FFND);
    tsplit_kernel<<<dim3(FFND / 32, DM / 32, NE),  dim3(32, 8)>>>(W2, p_w2hi, p_w2lo, FFND, DM);

    // xg = x @ Wih^T + bih (HMMA bf16x3)
    hmma_gemm<<<dim3(NWALL / 128, NTOK / 128, 1), 256, HMMA_SMEM>>>(
        p_xhi, p_xlo, DM, p_whi, p_wlo, DM, bih, 0,
        p_xg, nullptr, nullptr, NWALL, NTOK, NWALL, DM, 0, 0, 0, 0L);

    // bidirectional GRU (persistent)
    gru_persist<<<GRU_CTAS, 512, GRU_SMEM>>>(Whh, bhh);

    gate_kernel<<<NTOK / 8, 256>>>(gW, gb);

    // expert GEMM1 + GELU -> h1 (bf16 split out)
    hmma_gemm<<<dim3(FFND / 128, 64, NE), 256, HMMA_SMEM>>>(
        p_fhi, p_flo, GOUT, p_w1hi, p_w1lo, GOUT, b1, FFND,
        nullptr, p_h1hi, p_h1lo, FFND, 0, FFND, GOUT, 1, 1, 1, (long)GOUT * FFND);

    // expert GEMM2 -> obuf (fp32)
    hmma_gemm<<<dim3(DM / 128, 64, NE), 256, HMMA_SMEM>>>(
        p_h1hi, p_h1lo, FFND, p_w2hi, p_w2lo, FFND, b2, DM,
        p_obuf, nullptr, nullptr, DM, 0, DM, FFND, 1, 0, 0, (long)FFND * DM);

    combine_kernel<<<(NTOK * DM + 255) / 256, 256>>>(out);
    aux_kernel<<<1, 1>>>(out, out_size);
}

// round 16
// speedup vs baseline: 1.1452x; 1.1452x over previous
#include <cuda_runtime.h>
#include <cuda_bf16.h>
#include <cstdint>
#include <math.h>

// ---------------- problem constants ----------------
#define BATCHN 8
#define TLEN   1024
#define DM     512
#define HH     1024
#define K3H    3072
#define NWALL  6144
#define NTOK   8192
#define GOUT   2048
#define FFND   2048
#define NE     8
#define GRU_CTAS 128
#define DIR_CTAS 64
#define GRU_SMEM ((16 * 3 * HH + BATCHN * HH + 16 * 48) * 4)
#define HMMA_SMEM 65536      // 2 buf x 4 arrays x 8KB

typedef unsigned long long u64;
typedef __nv_bfloat16 bf16;

// ---------------- packed fp32x2 helpers (GRU) ----------------
__device__ __forceinline__ u64 pk2(float x) {
    u64 r; asm("mov.b64 %0, {%1, %1};" : "=l"(r) : "f"(x)); return r;
}
__device__ __forceinline__ void fma2(u64& d, u64 a, u64 b) {
    asm("fma.rn.f32x2 %0, %1, %2, %0;" : "+l"(d) : "l"(a), "l"(b));
}
__device__ __forceinline__ float2 upk(u64 v) {
    float2 f; asm("mov.b64 {%0, %1}, %2;" : "=f"(f.x), "=f"(f.y) : "l"(v)); return f;
}
union F4U { float4 f; u64 u[2]; };

// ---------------- HMMA helpers ----------------
__device__ __forceinline__ uint32_t smem_u32(const void* p) {
    uint32_t a;
    asm("{ .reg .u64 t; cvta.to.shared.u64 t, %1; cvt.u32.u64 %0, t; }" : "=r"(a) : "l"(p));
    return a;
}
__device__ __forceinline__ void ldsm4(uint32_t& r0, uint32_t& r1, uint32_t& r2,
                                      uint32_t& r3, uint32_t addr) {
    asm volatile("ldmatrix.sync.aligned.m8n8.x4.shared.b16 {%0,%1,%2,%3}, [%4];"
                 : "=r"(r0), "=r"(r1), "=r"(r2), "=r"(r3) : "r"(addr));
}
__device__ __forceinline__ void mma_bf16(float* d, const uint32_t* a,
                                         uint32_t b0, uint32_t b1) {
    asm volatile("mma.sync.aligned.m16n8k16.row.col.f32.bf16.bf16.f32 "
        "{%0,%1,%2,%3}, {%4,%5,%6,%7}, {%8,%9}, {%0,%1,%2,%3};"
        : "+f"(d[0]), "+f"(d[1]), "+f"(d[2]), "+f"(d[3])
        : "r"(a[0]), "r"(a[1]), "r"(a[2]), "r"(a[3]), "r"(b0), "r"(b1));
}
__device__ __forceinline__ uint32_t toff(int r, int s) {
    return (uint32_t)(r * 64 + ((s ^ ((r >> 1) & 3)) << 4));
}
__device__ __forceinline__ unsigned pack_bf16(float x0, float x1, unsigned& loOut) {
    bf16 h0 = __float2bfloat16(x0);
    bf16 h1 = __float2bfloat16(x1);
    bf16 l0 = __float2bfloat16(x0 - __bfloat162float(h0));
    bf16 l1 = __float2bfloat16(x1 - __bfloat162float(h1));
    unsigned short uh0 = *(unsigned short*)&h0, uh1 = *(unsigned short*)&h1;
    unsigned short ul0 = *(unsigned short*)&l0, ul1 = *(unsigned short*)&l1;
    loOut = (unsigned)ul0 | ((unsigned)ul1 << 16);
    return (unsigned)uh0 | ((unsigned)uh1 << 16);
}

// ---------------- static device scratch ----------------
__device__ float g_xg[(size_t)NTOK * NWALL];
__device__ float g_flat[(size_t)NTOK * GOUT];
__device__ float g_obuf[(size_t)NTOK * 2 * DM];
__device__ float g_hbuf[2][2][BATCHN * HH];
__device__ int   g_list[NE][NTOK];
__device__ int   g_cnt[NE];
__device__ float g_wt[NTOK * 2];
__device__ float g_Psum[NE];
__device__ float g_zsum;
__device__ volatile int g_flag[2][DIR_CTAS][32];   // padded: 1 flag / 128B line
// bf16 split operands
__device__ bf16 g_xhi[(size_t)NTOK * DM],    g_xlo[(size_t)NTOK * DM];
__device__ bf16 g_whi[(size_t)NWALL * DM],   g_wlo[(size_t)NWALL * DM];
__device__ bf16 g_fhi[(size_t)NTOK * GOUT],  g_flo[(size_t)NTOK * GOUT];
__device__ bf16 g_w1hi[(size_t)NE * GOUT * FFND], g_w1lo[(size_t)NE * GOUT * FFND];
__device__ bf16 g_h1hi[(size_t)NTOK * 2 * FFND],  g_h1lo[(size_t)NTOK * 2 * FFND];
__device__ bf16 g_w2hi[(size_t)NE * FFND * DM],   g_w2lo[(size_t)NE * FFND * DM];

extern __shared__ char smem_raw[];

// ---------------- init ----------------
__global__ void init_kernel() {
    int i = blockIdx.x * blockDim.x + threadIdx.x;
    float* h0 = &g_hbuf[0][0][0];
    if (i < 2 * 2 * BATCHN * HH) h0[i] = 0.f;
    if (i < NE) { g_cnt[i] = 0; g_Psum[i] = 0.f; }
    if (i < 2 * DIR_CTAS) g_flag[i >> 6][i & 63][0] = 0;
    if (i == 0) g_zsum = 0.f;
}

// ---------------- bf16 split (paired, 4B stores) ----------------
__global__ void split_kernel(const float* __restrict__ src,
                             bf16* __restrict__ hi, bf16* __restrict__ lo, size_t npair) {
    size_t i = (size_t)blockIdx.x * blockDim.x + threadIdx.x;
    if (i >= npair) return;
    float2 x = ((const float2*)src)[i];
    unsigned lv, hv = pack_bf16(x.x, x.y, lv);
    ((unsigned*)hi)[i] = hv;
    ((unsigned*)lo)[i] = lv;
}

// W [e][K][N] -> hi/lo [e][N][K], transposed, paired 4B stores over k
__global__ void tsplit_kernel(const float* __restrict__ W,
                              bf16* __restrict__ hi, bf16* __restrict__ lo, int K, int N) {
    __shared__ float tile[64][33];   // [k][n]
    int e = blockIdx.z;
    const float* We = W + (size_t)e * K * N;
    unsigned* hip = (unsigned*)(hi + (size_t)e * K * N);
    unsigned* lop = (unsigned*)(lo + (size_t)e * K * N);
    int k0 = blockIdx.x * 64, n0 = blockIdx.y * 32;
    int tx = threadIdx.x, ty = threadIdx.y;        // 32 x 8
    #pragma unroll
    for (int r = 0; r < 64; r += 8)
        tile[ty + r][tx] = We[(size_t)(k0 + ty + r) * N + n0 + tx];
    __syncthreads();
    #pragma unroll
    for (int rr = 0; rr < 32; rr += 8) {
        int nloc = ty + rr;
        float x0 = tile[tx * 2][nloc];
        float x1 = tile[tx * 2 + 1][nloc];
        unsigned lv, hv = pack_bf16(x0, x1, lv);
        size_t o = ((size_t)(n0 + nloc) * K + k0) / 2 + tx;
        hip[o] = hv;
        lop[o] = lv;
    }
}

// ---------------- HMMA bf16x3 GEMM (R13 winner, unchanged) ----------------------
__global__ void __launch_bounds__(256) hmma_gemm(
    const bf16* __restrict__ Ahi, const bf16* __restrict__ Alo, int lda,
    const bf16* __restrict__ Bhi, const bf16* __restrict__ Blo, int ldb,
    const float* __restrict__ bias, int biasPerExp,
    float* Cf, bf16* Chi, bf16* Clo, int ldc,
    int M, int N, int K,
    int useList, int aDiv, int act, long bStrideB)
{
    char* smem = smem_raw;
    const int tid = threadIdx.x;
    const int* glist = nullptr;
    if (useList) {
        int e = blockIdx.z;
        M = g_cnt[e];
        glist = g_list[e];
        Bhi += (size_t)bStrideB * e;
        Blo += (size_t)bStrideB * e;
        bias += (size_t)biasPerExp * e;
    }
    int m0 = blockIdx.y * 128;
    if (m0 >= M) return;
    int n0 = blockIdx.x * 128;

    uint32_t sb = smem_u32(smem);
    int warp = tid >> 5, lane = tid & 31;
    int wm = warp & 3, wn = warp >> 2;

    int srow = tid >> 1;
    int ss0 = (tid & 1) * 2;
    int mA = m0 + srow;
    bool aValid = (mA < M);
    size_t arow = 0;
    if (aValid) { if (glist) { int gv = glist[mA]; arow = (size_t)(aDiv ? (gv >> 1) : gv); }
                  else arow = (size_t)mA; }
    const uint4* Aph = (const uint4*)(Ahi + arow * (size_t)lda);
    const uint4* Apl = (const uint4*)(Alo + arow * (size_t)lda);
    const uint4* Bph = (const uint4*)(Bhi + (size_t)(n0 + srow) * ldb);
    const uint4* Bpl = (const uint4*)(Blo + (size_t)(n0 + srow) * ldb);
    uint32_t wo0 = toff(srow, ss0);
    uint32_t wo1 = toff(srow, ss0 + 1);

    int laneRowA = (((lane >> 3) & 1) << 3) + (lane & 7);
    int laneSegA = lane >> 4;
    int laneRowB = ((lane >> 4) << 3) + (lane & 7);
    int laneSegB = (lane >> 3) & 1;

    float acc[2][8][4];
    #pragma unroll
    for (int a = 0; a < 2; a++)
        #pragma unroll
        for (int b = 0; b < 8; b++)
            #pragma unroll
            for (int c = 0; c < 4; c++) acc[a][b][c] = 0.f;

    const uint4 z4 = make_uint4(0u, 0u, 0u, 0u);
    int nchunks = K >> 5;

    uint4 va0 = aValid ? __ldg(&Aph[ss0]) : z4;
    uint4 va1 = aValid ? __ldg(&Aph[ss0 + 1]) : z4;
    uint4 vb0 = aValid ? __ldg(&Apl[ss0]) : z4;
    uint4 vb1 = aValid ? __ldg(&Apl[ss0 + 1]) : z4;
    uint4 vc0 = __ldg(&Bph[ss0]);
    uint4 vc1 = __ldg(&Bph[ss0 + 1]);
    uint4 vd0 = __ldg(&Bpl[ss0]);
    uint4 vd1 = __ldg(&Bpl[ss0 + 1]);

    int buf = 0;
    for (int c = 0; c < nchunks; c++) {
        char* bp = smem + buf * 32768;
        *(uint4*)(bp + wo0)          = va0;
        *(uint4*)(bp + wo1)          = va1;
        *(uint4*)(bp + 8192  + wo0)  = vb0;
        *(uint4*)(bp + 8192  + wo1)  = vb1;
        *(uint4*)(bp + 16384 + wo0)  = vc0;
        *(uint4*)(bp + 16384 + wo1)  = vc1;
        *(uint4*)(bp + 24576 + wo0)  = vd0;
        *(uint4*)(bp + 24576 + wo1)  = vd1;
        __syncthreads();

        if (c + 1 < nchunks) {
            int gs = (c + 1) * 4 + ss0;
            va0 = aValid ? __ldg(&Aph[gs]) : z4;
            va1 = aValid ? __ldg(&Aph[gs + 1]) : z4;
            vb0 = aValid ? __ldg(&Apl[gs]) : z4;
            vb1 = aValid ? __ldg(&Apl[gs + 1]) : z4;
            vc0 = __ldg(&Bph[gs]);
            vc1 = __ldg(&Bph[gs + 1]);
            vd0 = __ldg(&Bpl[gs]);
            vd1 = __ldg(&Bpl[gs + 1]);
        }

        uint32_t base = sb + buf * 32768;
        #pragma unroll
        for (int kstep = 0; kstep < 2; kstep++) {
            uint32_t ah[2][4], al[2][4];
            #pragma unroll
            for (int mt = 0; mt < 2; mt++) {
                int r = wm * 32 + mt * 16 + laneRowA;
                int s = kstep * 2 + laneSegA;
                uint32_t ad = base + toff(r, s);
                ldsm4(ah[mt][0], ah[mt][1], ah[mt][2], ah[mt][3], ad);
                ldsm4(al[mt][0], al[mt][1], al[mt][2], al[mt][3], ad + 8192);
            }
            #pragma unroll
            for (int np = 0; np < 4; np++) {
                int r = wn * 64 + np * 16 + laneRowB;
                int s = kstep * 2 + laneSegB;
                uint32_t bd = base + 16384 + toff(r, s);
                uint32_t bh[4], bl[4];
                ldsm4(bh[0], bh[1], bh[2], bh[3], bd);
                ldsm4(bl[0], bl[1], bl[2], bl[3], bd + 8192);
                #pragma unroll
                for (int mt = 0; mt < 2; mt++) {
                    mma_bf16(acc[mt][np * 2],     ah[mt], bh[0], bh[1]);
                    mma_bf16(acc[mt][np * 2 + 1], ah[mt], bh[2], bh[3]);
                    mma_bf16(acc[mt][np * 2],     ah[mt], bl[0], bl[1]);
                    mma_bf16(acc[mt][np * 2 + 1], ah[mt], bl[2], bl[3]);
                    mma_bf16(acc[mt][np * 2],     al[mt], bh[0], bh[1]);
                    mma_bf16(acc[mt][np * 2 + 1], al[mt], bh[2], bh[3]);
                }
            }
        }
        __syncthreads();
        buf ^= 1;
    }

    #pragma unroll
    for (int mt = 0; mt < 2; mt++) {
        #pragma unroll
        for (int rr = 0; rr < 2; rr++) {
            int m_loc = wm * 32 + mt * 16 + rr * 8 + (lane >> 2);
            int m = m0 + m_loc;
            if (m >= M) continue;
            size_t crow = glist ? (size_t)glist[m] : (size_t)m;
            #pragma unroll
            for (int nt = 0; nt < 8; nt++) {
                int n = n0 + wn * 64 + nt * 8 + (lane & 3) * 2;
                float v0 = acc[mt][nt][rr * 2]     + __ldg(&bias[n]);
                float v1 = acc[mt][nt][rr * 2 + 1] + __ldg(&bias[n + 1]);
                if (act) {
                    v0 = 0.5f * v0 * (1.0f + erff(v0 * 0.70710678118654752f));
                    v1 = 0.5f * v1 * (1.0f + erff(v1 * 0.70710678118654752f));
                }
                size_t o = crow * (size_t)ldc + n;
                if (Cf) {
                    *(float2*)(Cf + o) = make_float2(v0, v1);
                } else {
                    unsigned lv, hv = pack_bf16(v0, v1, lv);
                    *(unsigned*)(Chi + o) = hv;
                    *(unsigned*)(Clo + o) = lv;
                }
            }
        }
    }
}

// ---------------- padded flag-array grid barrier (per direction) ---------------
__device__ __forceinline__ void grid_sync_dir(int dir, int cta, int step) {
    __syncthreads();
    if (threadIdx.x == 0) {
        __threadfence();
        g_flag[dir][cta][0] = step;
    }
    if (threadIdx.x < DIR_CTAS) {
        while (g_flag[dir][threadIdx.x][0] < step) __nanosleep(32);
    }
    __syncthreads();
}

// ---------------- persistent bidirectional GRU (R14 winner, unchanged) ---------
__global__ void __launch_bounds__(512) gru_persist(
    const float* __restrict__ Whh, const float* __restrict__ bhh)
{
    float* smem = (float*)smem_raw;
    float* sw   = smem;
    float* hs   = smem + 16 * 3 * HH;
    float* sred = smem + 16 * 3 * HH + BATCHN * HH;
    int bx = blockIdx.x;
    int dir = bx >> 6;
    int cta = bx & 63;
    int warp = threadIdx.x >> 5;
    int lane = threadIdx.x & 31;

    int khalf = warp >> 3;
    int wp    = warp & 7;
    int bh    = lane >> 4;
    int kg    = lane & 15;

    {
        int jglob = cta * 16 + warp;
        const float* Wb = Whh + (size_t)dir * K3H * HH;
        #pragma unroll
        for (int g = 0; g < 3; g++) {
            const float4* src = (const float4*)(Wb + (size_t)(g * HH + jglob) * HH);
            float4* dst = (float4*)(sw + (warp * 3 + g) * HH);
            for (int kq = lane; kq < HH / 4; kq += 32)
                dst[kq] = src[kq];
        }
    }

    bool tail = (warp < 8) && (lane < 16);
    int tjj = wp * 2 + (lane >> 3);
    int tb  = lane & 7;
    int tj  = cta * 16 + tjj;
    float bh_r = 0.f, bh_z = 0.f, bh_n = 0.f;
    if (tail) {
        const float* bhp = bhh + dir * K3H;
        bh_r = bhp[tj]; bh_z = bhp[HH + tj]; bh_n = bhp[2 * HH + tj];
    }

    const F4U* wA[3];
    const F4U* wB[3];
    #pragma unroll
    for (int g = 0; g < 3; g++) {
        wA[g] = (const F4U*)(sw + ((wp * 2 + 0) * 3 + g) * HH);
        wB[g] = (const F4U*)(sw + ((wp * 2 + 1) * 3 + g) * HH);
    }
    const F4U* h4 = (const F4U*)hs;
    const int kbase = khalf * 128;

    for (int s = 0; s < TLEN; s++) {
        int t = dir ? (TLEN - 1 - s) : s;

        float xr = 0.f, xz = 0.f, xn = 0.f;
        if (tail) {
            const float* xgr = g_xg + (size_t)(tb * TLEN + t) * NWALL + (size_t)dir * K3H;
            xr = __ldg(&xgr[tj]);
            xz = __ldg(&xgr[HH + tj]);
            xn = __ldg(&xgr[2 * HH + tj]);
        }

        const float4* hprev = (const float4*)&g_hbuf[s & 1][dir][0];
        float4* hs4 = (float4*)hs;
        #pragma unroll
        for (int idx = threadIdx.x; idx < BATCHN * HH / 4; idx += 512)
            hs4[idx] = __ldcg(&hprev[idx]);
        __syncthreads();

        u64 acc[2][3][4];
        #pragma unroll
        for (int jj = 0; jj < 2; jj++)
            #pragma unroll
            for (int g = 0; g < 3; g++)
                #pragma unroll
                for (int b = 0; b < 4; b++) acc[jj][g][b] = 0ull;

        #pragma unroll
        for (int i = 0; i < 8; i++) {
            int kq = kbase + i * 16 + kg;
            F4U w0A = wA[0][kq], w1A = wA[1][kq], w2A = wA[2][kq];
            F4U w0B = wB[0][kq], w1B = wB[1][kq], w2B = wB[2][kq];
            #pragma unroll
            for (int b = 0; b < 4; b++) {
                F4U hv = h4[(bh * 4 + b) * 256 + kq];
                fma2(acc[0][0][b], w0A.u[0], hv.u[0]);
                fma2(acc[0][1][b], w1A.u[0], hv.u[0]);
                fma2(acc[0][2][b], w2A.u[0], hv.u[0]);
                fma2(acc[1][0][b], w0B.u[0], hv.u[0]);
                fma2(acc[1][1][b], w1B.u[0], hv.u[0]);
                fma2(acc[1][2][b], w2B.u[0], hv.u[0]);
                fma2(acc[0][0][b], w0A.u[1], hv.u[1]);
                fma2(acc[0][1][b], w1A.u[1], hv.u[1]);
                fma2(acc[0][2][b], w2A.u[1], hv.u[1]);
                fma2(acc[1][0][b], w0B.u[1], hv.u[1]);
                fma2(acc[1][1][b], w1B.u[1], hv.u[1]);
                fma2(acc[1][2][b], w2B.u[1], hv.u[1]);
            }
        }

        float red[2][3][4];
        #pragma unroll
        for (int jj = 0; jj < 2; jj++)
            #pragma unroll
            for (int g = 0; g < 3; g++)
                #pragma unroll
                for (int b = 0; b < 4; b++) {
                    float2 p = upk(acc[jj][g][b]);
                    red[jj][g][b] = p.x + p.y;
                }
        #pragma unroll
        for (int off = 8; off > 0; off >>= 1)
            #pragma unroll
            for (int jj = 0; jj < 2; jj++)
                #pragma unroll
                for (int g = 0; g < 3; g++)
                    #pragma unroll
                    for (int b = 0; b < 4; b++)
                        red[jj][g][b] += __shfl_xor_sync(0xffffffffu, red[jj][g][b], off);

        if (kg == 0) {
            float* dst = sred + warp * 48 + bh * 4;
            #pragma unroll
            for (int jj = 0; jj < 2; jj++)
                #pragma unroll
                for (int g = 0; g < 3; g++)
                    #pragma unroll
                    for (int b = 0; b < 4; b++)
                        dst[(jj * 3 + g) * 8 + b] = red[jj][g][b];
        }
        __syncthreads();

        if (tail) {
            int base = ((lane >> 3) * 3) * 8 + tb;
            const float* rA = sred + wp * 48;
            const float* rB = sred + (wp + 8) * 48;
            float hr = rA[base]      + rB[base]      + bh_r;
            float hz = rA[base + 8]  + rB[base + 8]  + bh_z;
            float hn = rA[base + 16] + rB[base + 16] + bh_n;
            float r  = 1.f / (1.f + expf(-(xr + hr)));
            float z  = 1.f / (1.f + expf(-(xz + hz)));
            float nn = tanhf(xn + r * hn);
            float hp = hs[tb * HH + tj];
            float hnew = (1.f - z) * nn + z * hp;
            g_hbuf[(s + 1) & 1][dir][tb * HH + tj] = hnew;
            float lrel = hnew > 0.f ? hnew : 0.01f * hnew;
            size_t o = (size_t)(tb * TLEN + t) * GOUT + dir * HH + tj;
            g_flat[o] = lrel;
            bf16 fh = __float2bfloat16(lrel);
            g_fhi[o] = fh;
            g_flo[o] = __float2bfloat16(lrel - __bfloat162float(fh));
        }
        grid_sync_dir(dir, cta, s + 1);
    }
}

// ---------------- gating: warp per token ----------------
__global__ void gate_kernel(const float* __restrict__ gW, const float* __restrict__ gb) {
    int gwid = (blockIdx.x * blockDim.x + threadIdx.x) >> 5;
    int lane = threadIdx.x & 31;
    if (gwid >= NTOK) return;
    const float* f = g_flat + (size_t)gwid * GOUT;
    float acc[NE];
    #pragma unroll
    for (int e = 0; e < NE; e++) acc[e] = 0.f;
    for (int k = lane; k < GOUT; k += 32) {
        float fv = f[k];
        #pragma unroll
        for (int e = 0; e < NE; e++) acc[e] = fmaf(fv, gW[e * GOUT + k], acc[e]);
    }
    #pragma unroll
    for (int e = 0; e < NE; e++)
        #pragma unroll
        for (int off = 16; off > 0; off >>= 1)
            acc[e] += __shfl_xor_sync(0xffffffffu, acc[e], off);

    if (lane == 0) {
        float l[NE], mx = -1e30f;
        #pragma unroll
        for (int e = 0; e < NE; e++) { l[e] = acc[e] + gb[e]; mx = fmaxf(mx, l[e]); }
        float se = 0.f;
        #pragma unroll
        for (int e = 0; e < NE; e++) se += expf(l[e] - mx);
        float lse = mx + logf(se);
        float sc[NE];
        #pragma unroll
        for (int e = 0; e < NE; e++) sc[e] = expf(l[e] - lse);
        int e0 = 0; float s0 = sc[0];
        #pragma unroll
        for (int e = 1; e < NE; e++) if (sc[e] > s0) { s0 = sc[e]; e0 = e; }
        int e1 = -1; float s1 = -1e30f;
        #pragma unroll
        for (int e = 0; e < NE; e++) if (e != e0 && sc[e] > s1) { s1 = sc[e]; e1 = e; }
        float inv = 1.f / (s0 + s1);
        int p0 = atomicAdd(&g_cnt[e0], 1);
        g_list[e0][p0] = gwid * 2;
        int p1 = atomicAdd(&g_cnt[e1], 1);
        g_list[e1][p1] = gwid * 2 + 1;
        g_wt[gwid * 2]     = s0 * inv;
        g_wt[gwid * 2 + 1] = s1 * inv;
        atomicAdd(&g_zsum, lse * lse);
        #pragma unroll
        for (int e = 0; e < NE; e++) atomicAdd(&g_Psum[e], sc[e]);
    }
}

// ---------------- deterministic combine ----------------
__global__ void combine_kernel(float* __restrict__ out) {
    int idx = blockIdx.x * blockDim.x + threadIdx.x;
    if (idx >= NTOK * DM) return;
    int t = idx >> 9;
    int d = idx & (DM - 1);
    out[idx] = g_wt[2 * t]     * g_obuf[(size_t)(2 * t) * DM + d]
             + g_wt[2 * t + 1] * g_obuf[(size_t)(2 * t + 1) * DM + d];
}

// ---------------- aux loss scalar ----------------
__global__ void aux_kernel(float* out, int out_size) {
    if (out_size <= NTOK * DM) return;
    float s = 0.f;
    #pragma unroll
    for (int e = 0; e < NE; e++)
        s += ((float)g_cnt[e] / (float)NTOK) * (g_Psum[e] / (float)NTOK);
    out[NTOK * DM] = 0.01f * (float)NE * s + 0.001f * (g_zsum / (float)NTOK);
}

// ---------------- launch ----------------
extern "C" void kernel_launch(void* const* d_in, const int* in_sizes, int n_in,
                              void* d_out, int out_size) {
    const float* x   = (const float*)d_in[0];
    const float* Wih = (const float*)d_in[1];
    const float* Whh = (const float*)d_in[2];
    const float* bih = (const float*)d_in[3];
    const float* bhh = (const float*)d_in[4];
    const float* gW  = (const float*)d_in[5];
    const float* gb  = (const float*)d_in[6];
    const float* W1  = (const float*)d_in[7];
    const float* b1  = (const float*)d_in[8];
    const float* W2  = (const float*)d_in[9];
    const float* b2  = (const float*)d_in[10];
    float* out = (float*)d_out;

    float *p_xg, *p_flat, *p_obuf;
    cudaGetSymbolAddress((void**)&p_xg,   g_xg);
    cudaGetSymbolAddress((void**)&p_flat, g_flat);
    cudaGetSymbolAddress((void**)&p_obuf, g_obuf);
    bf16 *p_xhi, *p_xlo, *p_whi, *p_wlo, *p_fhi, *p_flo;
    bf16 *p_w1hi, *p_w1lo, *p_h1hi, *p_h1lo, *p_w2hi, *p_w2lo;
    cudaGetSymbolAddress((void**)&p_xhi,  g_xhi);
    cudaGetSymbolAddress((void**)&p_xlo,  g_xlo);
    cudaGetSymbolAddress((void**)&p_whi,  g_whi);
    cudaGetSymbolAddress((void**)&p_wlo,  g_wlo);
    cudaGetSymbolAddress((void**)&p_fhi,  g_fhi);
    cudaGetSymbolAddress((void**)&p_flo,  g_flo);
    cudaGetSymbolAddress((void**)&p_w1hi, g_w1hi);
    cudaGetSymbolAddress((void**)&p_w1lo, g_w1lo);
    cudaGetSymbolAddress((void**)&p_h1hi, g_h1hi);
    cudaGetSymbolAddress((void**)&p_h1lo, g_h1lo);
    cudaGetSymbolAddress((void**)&p_w2hi, g_w2hi);
    cudaGetSymbolAddress((void**)&p_w2lo, g_w2lo);

    cudaFuncSetAttribute(gru_persist,
                         cudaFuncAttributeMaxDynamicSharedMemorySize, GRU_SMEM);
    cudaFuncSetAttribute(hmma_gemm,
                         cudaFuncAttributeMaxDynamicSharedMemorySize, HMMA_SMEM);

    init_kernel<<<256, 256>>>();

    // bf16 splits (paired stores; flat split fused into GRU tail)
    split_kernel<<<(NTOK * DM / 2 + 255) / 256, 256>>>(x, p_xhi, p_xlo, (size_t)NTOK * DM / 2);
    split_kernel<<<(NWALL * DM / 2 + 255) / 256, 256>>>(Wih, p_whi, p_wlo, (size_t)NWALL * DM / 2);
    tsplit_kernel<<<dim3(GOUT / 64, FFND / 32, NE), dim3(32, 8)>>>(W1, p_w1hi, p_w1lo, GOUT, FFND);
    tsplit_kernel<<<dim3(FFND / 64, DM / 32, NE),  dim3(32, 8)>>>(W2, p_w2hi, p_w2lo, FFND, DM);

    // xg = x @ Wih^T + bih (HMMA bf16x3)
    hmma_gemm<<<dim3(NWALL / 128, NTOK / 128, 1), 256, HMMA_SMEM>>>(
        p_xhi, p_xlo, DM, p_whi, p_wlo, DM, bih, 0,
        p_xg, nullptr, nullptr, NWALL, NTOK, NWALL, DM, 0, 0, 0, 0L);

    // bidirectional GRU (persistent, padded-flag barrier, fused flat split)
    gru_persist<<<GRU_CTAS, 512, GRU_SMEM>>>(Whh, bhh);

    gate_kernel<<<NTOK / 8, 256>>>(gW, gb);

    // expert GEMM1 + GELU -> h1 (bf16 split out)
    hmma_gemm<<<dim3(FFND / 128, 64, NE), 256, HMMA_SMEM>>>(
        p_fhi, p_flo, GOUT, p_w1hi, p_w1lo, GOUT, b1, FFND,
        nullptr, p_h1hi, p_h1lo, FFND, 0, FFND, GOUT, 1, 1, 1, (long)GOUT * FFND);

    // expert GEMM2 -> obuf (fp32)
    hmma_gemm<<<dim3(DM / 128, 64, NE), 256, HMMA_SMEM>>>(
        p_h1hi, p_h1lo, FFND, p_w2hi, p_w2lo, FFND, b2, DM,
        p_obuf, nullptr, nullptr, DM, 0, DM, FFND, 1, 0, 0, (long)FFND * DM);

    combine_kernel<<<(NTOK * DM + 255) / 256, 256>>>(out);
    aux_kernel<<<1, 1>>>(out, out_size);
}